// round 6
// baseline (speedup 1.0000x reference)
#include <cuda_runtime.h>
#include <math.h>

#define BB 64
#define PP 2048
#define LL 512
#define DM 512
#define HH 8
#define RCH 32                // rows per chunk
#define NCH (PP / RCH)        // 64 chunks per batch
#define LN_EPS 1e-5f

// ---------------- scratch (device globals; no allocation) ----------------
__device__ float g_wg[BB * HH * LL];               // gamma-folded (1/8)W_k^T Q  [b][h][l]
__device__ float g_Wsum[BB * HH];
__device__ float g_wb[BB * HH];
__device__ float g_resid[BB * DM];
__device__ float g_scores[(size_t)BB * PP * HH];   // [b][p][h]
__device__ float g_cmax[BB * NCH * HH];            // [(b*NCH+c)*HH+h]
__device__ float g_cse[BB * NCH * HH];
__device__ float g_ca2[BB * NCH * HH];
__device__ float g_fact[BB * NCH * HH];
__device__ float g_M[BB * HH];
__device__ float g_invZ[BB * HH];
__device__ float g_acc2[BB * HH];
__device__ float g_spart[(size_t)BB * NCH * HH * LL];  // 67 MB partial weighted sums
__device__ float g_svec[BB * HH * LL];             // reduced, LN-corrected s vectors

// ---------------- K1: per-batch setup (2 blocks per batch) -----------------
__global__ void k1_setup(const float* __restrict__ xt,
                         const float* __restrict__ Wq,
                         const float* __restrict__ Wk,
                         const float* __restrict__ lnqg, const float* __restrict__ lnqb,
                         const float* __restrict__ lnkvg, const float* __restrict__ lnkvb,
                         const float* __restrict__ resW, const float* __restrict__ resb) {
    int half = blockIdx.x, b = blockIdx.y, t = threadIdx.x;
    __shared__ float sx[LL];
    __shared__ float sq[LL];
    __shared__ float sQ[DM];          // only this half's 256 entries filled
    __shared__ float sred[24];
    __shared__ float sws[4][2], swbp[4][2];

    float x0 = xt[b * LL + t];
    float x1 = xt[b * LL + t + 256];
    sx[t] = x0; sx[t + 256] = x1;

    float ps = x0 + x1;
    float pq = x0 * x0 + x1 * x1;
    #pragma unroll
    for (int o = 16; o; o >>= 1) {
        ps += __shfl_xor_sync(~0u, ps, o);
        pq += __shfl_xor_sync(~0u, pq, o);
    }
    if ((t & 31) == 0) { sred[t >> 5] = ps; sred[8 + (t >> 5)] = pq; }
    __syncthreads();
    if (t == 0) {
        float s = 0.f, q = 0.f;
        for (int i = 0; i < 8; i++) { s += sred[i]; q += sred[8 + i]; }
        float m = s * (1.0f / LL);
        float v = q * (1.0f / LL) - m * m;
        sred[16] = m;
        sred[17] = rsqrtf(v + LN_EPS);
    }
    __syncthreads();
    float mean = sred[16], rstd = sred[17];
    sq[t]       = (x0 - mean) * rstd * lnqg[t]       + lnqb[t];
    sq[t + 256] = (x1 - mean) * rstd * lnqg[t + 256] + lnqb[t + 256];
    __syncthreads();

    // this half's 256 output columns: Q GEMV + residual GEMV (coalesced)
    int d = half * 256 + t;
    {
        float qa = 0.f, ra = 0.f;
        #pragma unroll 8
        for (int l = 0; l < LL; l++) {
            qa = fmaf(sq[l], Wq[(size_t)l * DM + d], qa);
            ra = fmaf(sx[l], resW[(size_t)l * DM + d], ra);
        }
        sQ[d] = qa;
        g_resid[b * DM + d] = ra + resb[d];
    }
    __syncthreads();

    // fold W_k through Q for heads [half*4, half*4+4): warp-per-(head, l%2)
    {
        int w = t >> 5, lane = t & 31;
        int hl = w >> 1;                 // 0..3
        int h  = half * 4 + hl;
        const float* Qh = sQ + h * 64;
        float q0 = Qh[lane], q1 = Qh[lane + 32];
        float wsum = 0.f, wbp = 0.f;
        for (int l = (w & 1); l < LL; l += 2) {
            const float* row = Wk + (size_t)l * DM + h * 64;
            float a = row[lane] * q0 + row[lane + 32] * q1;
            #pragma unroll
            for (int o = 16; o; o >>= 1) a += __shfl_xor_sync(~0u, a, o);
            float wv = a * 0.125f;       // 1/sqrt(64)
            float gw = wv * lnkvg[l];
            if (lane == 0) g_wg[((size_t)b * HH + h) * LL + l] = gw;
            wsum += gw;
            wbp  += wv * lnkvb[l];
        }
        if (lane == 0) { sws[hl][w & 1] = wsum; swbp[hl][w & 1] = wbp; }
    }
    __syncthreads();
    if (t < 4) {
        g_Wsum[b * HH + half * 4 + t] = sws[t][0] + sws[t][1];
        g_wb[b * HH + half * 4 + t]   = swbp[t][0] + swbp[t][1];
    }
}

// ---------------- K24: fused score + partial-softmax + weighted-sum --------
// One block per (chunk of 32 rows, batch). x tile staged in SMEM; single DRAM pass.
#define K24_SMEM_FLOATS (RCH*LL + HH*LL + 4224 + RCH*HH + 256 + 256 + RCH + RCH + HH + HH + HH)
__global__ void __launch_bounds__(256) k24_fused(const float* __restrict__ xd) {
    int c = blockIdx.x, b = blockIdx.y, t = threadIdx.x;
    int wid = t >> 5, lane = t & 31;

    extern __shared__ float smem[];
    float* sx     = smem;                 // RCH*LL = 16384
    float* swg    = sx + RCH * LL;        // HH*LL  = 4096
    float* scomb  = swg + HH * LL;        // 4224 (stride-33 padded)
    float* scoeff = scomb + 4224;         // RCH*HH = 256 (scores, then e*rstd)
    float* sredE  = scoeff + RCH * HH;    // 256
    float* sredA  = sredE + 256;          // 256
    float* smean  = sredA + 256;          // RCH
    float* srstd  = smean + RCH;          // RCH
    float* scmax  = srstd + RCH;          // HH
    float* sWs    = scmax + HH;           // HH
    float* swb    = sWs + HH;             // HH

    // load folded weight vectors
    {
        const float4* wgb = (const float4*)(g_wg + (size_t)b * HH * LL);
        float4* swg4 = (float4*)swg;
        for (int i = t; i < HH * LL / 4; i += 256) swg4[i] = wgb[i];
        if (t < HH) { sWs[t] = g_Wsum[b * HH + t]; swb[t] = g_wb[b * HH + t]; }
    }
    __syncthreads();

    int p0 = c * RCH;

    // ---- stage A: warp per row; stream x from DRAM, stage into smem, score
    for (int r = wid; r < RCH; r += 8) {
        int p = p0 + r;
        const float4* xr = (const float4*)(xd + ((size_t)b * PP + p) * LL);
        float4 xv[4];
        #pragma unroll
        for (int j = 0; j < 4; j++) xv[j] = xr[lane + 32 * j];
        float4* sxr = (float4*)(sx + r * LL);
        #pragma unroll
        for (int j = 0; j < 4; j++) sxr[lane + 32 * j] = xv[j];

        float s = 0.f, q = 0.f;
        #pragma unroll
        for (int j = 0; j < 4; j++) {
            s += xv[j].x + xv[j].y + xv[j].z + xv[j].w;
            q += xv[j].x * xv[j].x + xv[j].y * xv[j].y
               + xv[j].z * xv[j].z + xv[j].w * xv[j].w;
        }
        float dot[HH];
        const float4* swg4 = (const float4*)swg;
        #pragma unroll
        for (int h = 0; h < HH; h++) {
            float a = 0.f;
            #pragma unroll
            for (int j = 0; j < 4; j++) {
                float4 wv = swg4[h * 128 + lane + 32 * j];
                a = fmaf(xv[j].x, wv.x, a);
                a = fmaf(xv[j].y, wv.y, a);
                a = fmaf(xv[j].z, wv.z, a);
                a = fmaf(xv[j].w, wv.w, a);
            }
            dot[h] = a;
        }
        #pragma unroll
        for (int o = 16; o; o >>= 1) {
            s += __shfl_xor_sync(~0u, s, o);
            q += __shfl_xor_sync(~0u, q, o);
            #pragma unroll
            for (int h = 0; h < HH; h++) dot[h] += __shfl_xor_sync(~0u, dot[h], o);
        }
        float m  = s * (1.0f / LL);
        float v  = q * (1.0f / LL) - m * m;
        float r_ = rsqrtf(v + LN_EPS);
        if (lane == 0) { smean[r] = m; srstd[r] = r_; }
        if (lane < HH) {
            float myd = 0.f, myWs = 0.f, mywb = 0.f;
            #pragma unroll
            for (int h = 0; h < HH; h++)
                if (lane == h) { myd = dot[h]; myWs = sWs[h]; mywb = swb[h]; }
            float sc = r_ * (myd - m * myWs) + mywb;
            g_scores[((size_t)b * PP + p) * HH + lane] = sc;
            scoeff[r * HH + lane] = sc;     // raw score for now
        }
    }
    __syncthreads();

    // ---- chunk max per head
    if (t < HH) {
        float m = -1e30f;
        for (int r = 0; r < RCH; r++) m = fmaxf(m, scoeff[r * HH + t]);
        scmax[t] = m;
    }
    __syncthreads();

    // ---- exp + partials (256 threads == RCH*HH)
    {
        int r = t >> 3, h = t & 7;
        float e  = __expf(scoeff[t] - scmax[h]);
        float rr = srstd[r];
        scoeff[t] = e * rr;                 // coefficient for weighted sum
        sredE[t]  = e;
        sredA[t]  = e * rr * smean[r];
    }
    __syncthreads();
    if (t < HH) {
        float se = 0.f, sa = 0.f;
        for (int k = 0; k < RCH; k++) { se += sredE[t + 8 * k]; sa += sredA[t + 8 * k]; }
        int o = (b * NCH + c) * HH + t;
        g_cse[o] = se; g_ca2[o] = sa; g_cmax[o] = scmax[t];
    }

    // ---- stage B: rank-1 accumulate from SMEM (2 rows in flight)
    int rowoff = t >> 7, col4 = t & 127;
    float4 acc[HH];
    #pragma unroll
    for (int h = 0; h < HH; h++) acc[h] = make_float4(0.f, 0.f, 0.f, 0.f);

    const float4* sx4  = (const float4*)sx;
    const float4* sco4 = (const float4*)scoeff;
    #pragma unroll 4
    for (int rb = 0; rb < RCH; rb += 2) {
        int r = rb + rowoff;
        float4 xv = sx4[r * 128 + col4];
        float4 c0 = sco4[r * 2], c1 = sco4[r * 2 + 1];
        float cc[8] = {c0.x, c0.y, c0.z, c0.w, c1.x, c1.y, c1.z, c1.w};
        #pragma unroll
        for (int h = 0; h < HH; h++) {
            acc[h].x = fmaf(cc[h], xv.x, acc[h].x);
            acc[h].y = fmaf(cc[h], xv.y, acc[h].y);
            acc[h].z = fmaf(cc[h], xv.z, acc[h].z);
            acc[h].w = fmaf(cc[h], xv.w, acc[h].w);
        }
    }
    if (rowoff == 1) {
        float* dst = scomb + col4 * 33;
        #pragma unroll
        for (int h = 0; h < HH; h++) {
            dst[h * 4 + 0] = acc[h].x; dst[h * 4 + 1] = acc[h].y;
            dst[h * 4 + 2] = acc[h].z; dst[h * 4 + 3] = acc[h].w;
        }
    }
    __syncthreads();
    if (rowoff == 0) {
        const float* src = scomb + col4 * 33;
        #pragma unroll
        for (int h = 0; h < HH; h++) {
            float4 o;
            o.x = acc[h].x + src[h * 4 + 0];
            o.y = acc[h].y + src[h * 4 + 1];
            o.z = acc[h].z + src[h * 4 + 2];
            o.w = acc[h].w + src[h * 4 + 3];
            ((float4*)(g_spart + (((size_t)(b * NCH + c)) * HH + h) * LL))[col4] = o;
        }
    }
}

// ---------------- K3c: combine chunk softmax stats -------------------------
__global__ void k3_combine() {
    int b = blockIdx.x, t = threadIdx.x;
    int h = t >> 5, lane = t & 31;          // warp per head, lane handles 2 chunks
    size_t base = (size_t)b * NCH * HH;
    float m0 = g_cmax[base + lane * HH + h];
    float m1 = g_cmax[base + (lane + 32) * HH + h];
    float M = fmaxf(m0, m1);
    #pragma unroll
    for (int o = 16; o; o >>= 1) M = fmaxf(M, __shfl_xor_sync(~0u, M, o));
    float e0 = __expf(m0 - M), e1 = __expf(m1 - M);
    float z = g_cse[base + lane * HH + h] * e0 + g_cse[base + (lane + 32) * HH + h] * e1;
    #pragma unroll
    for (int o = 16; o; o >>= 1) z += __shfl_xor_sync(~0u, z, o);
    float invZ = 1.0f / z;
    float f0 = e0 * invZ, f1 = e1 * invZ;
    g_fact[base + lane * HH + h] = f0;
    g_fact[base + (lane + 32) * HH + h] = f1;
    float a2 = g_ca2[base + lane * HH + h] * f0 + g_ca2[base + (lane + 32) * HH + h] * f1;
    #pragma unroll
    for (int o = 16; o; o >>= 1) a2 += __shfl_xor_sync(~0u, a2, o);
    if (lane == 0) {
        g_M[b * HH + h] = M;
        g_invZ[b * HH + h] = invZ;
        g_acc2[b * HH + h] = a2;
    }
}

// ---------------- K_attn: write attn output (transposed, coalesced) --------
__global__ void k_attn(float* __restrict__ out_attn) {
    int tile = blockIdx.x, b = blockIdx.y, t = threadIdx.x;
    __shared__ float satt[256 * 9];
    __shared__ float sM[HH], sI[HH];
    if (t < HH) { sM[t] = g_M[b * HH + t]; sI[t] = g_invZ[b * HH + t]; }
    __syncthreads();
    const float* sc = g_scores + ((size_t)b * PP + tile * 256) * HH;
    #pragma unroll
    for (int k = 0; k < 8; k++) {
        int il = k * 256 + t;
        int pl = il >> 3, h = il & 7;
        satt[pl * 9 + h] = __expf(sc[il] - sM[h]) * sI[h];
    }
    __syncthreads();
    #pragma unroll
    for (int k = 0; k < 8; k++)
        out_attn[((size_t)b * HH + k) * PP + tile * 256 + t] = satt[t * 9 + k];
}

// ---------------- K5a: rescale-reduce partials per (b,h), LN correction ----
__global__ void k5a_reduce(const float* __restrict__ lnkvg,
                           const float* __restrict__ lnkvb) {
    int h = blockIdx.x, b = blockIdx.y, t = threadIdx.x;
    __shared__ float sf[NCH];
    if (t < NCH) sf[t] = g_fact[(size_t)b * NCH * HH + t * HH + h];
    __syncthreads();

    // 256 threads, 2 columns each
    float a0 = 0.f, a1 = 0.f;
    const float* sp = g_spart + ((size_t)(b * NCH) * HH + h) * LL;
    #pragma unroll 8
    for (int c = 0; c < NCH; c++) {
        float f = sf[c];
        const float* row = sp + (size_t)c * HH * LL;
        a0 = fmaf(f, row[t], a0);
        a1 = fmaf(f, row[t + 256], a1);
    }
    float acc2 = g_acc2[b * HH + h];
    float* dst = g_svec + ((size_t)b * HH + h) * LL;
    dst[t]       = lnkvg[t]       * (a0 - acc2) + lnkvb[t];
    dst[t + 256] = lnkvg[t + 256] * (a1 - acc2) + lnkvb[t + 256];
}

// ---------------- K5b: V-GEMV + residual add -------------------------------
__global__ void k5b_out(const float* __restrict__ Wv,
                        float* __restrict__ out_ctx) {
    int b = blockIdx.x, t = threadIdx.x;
    __shared__ float ss[HH * LL];     // 16 KB
    const float4* sv = (const float4*)(g_svec + (size_t)b * HH * LL);
    float4* ss4 = (float4*)ss;
    for (int i = t; i < HH * LL / 4; i += 512) ss4[i] = sv[i];
    __syncthreads();

    int d = t;                        // 512 threads, one output column each
    int h = d >> 6;
    const float* sh = ss + h * LL;
    float a = 0.f;
    #pragma unroll 8
    for (int l = 0; l < LL; l++) a = fmaf(sh[l], Wv[(size_t)l * DM + d], a);
    out_ctx[b * DM + d] = g_resid[b * DM + d] + a;
}

// ---------------- launch ---------------------------------------------------
extern "C" void kernel_launch(void* const* d_in, const int* in_sizes, int n_in,
                              void* d_out, int out_size) {
    const float* xt    = (const float*)d_in[0];
    const float* xd    = (const float*)d_in[1];
    const float* Wq    = (const float*)d_in[3];
    const float* Wk    = (const float*)d_in[4];
    const float* Wv    = (const float*)d_in[5];
    const float* lnqg  = (const float*)d_in[6];
    const float* lnqb  = (const float*)d_in[7];
    const float* lnkvg = (const float*)d_in[8];
    const float* lnkvb = (const float*)d_in[9];
    const float* resW  = (const float*)d_in[10];
    const float* resb  = (const float*)d_in[11];

    float* out      = (float*)d_out;
    float* out_ctx  = out;                  // (B, DM)
    float* out_attn = out + BB * DM;        // (B, H, 1, P)

    const int k24_smem = K24_SMEM_FLOATS * (int)sizeof(float);
    cudaFuncSetAttribute(k24_fused, cudaFuncAttributeMaxDynamicSharedMemorySize, k24_smem);

    k1_setup<<<dim3(2, BB), 256>>>(xt, Wq, Wk, lnqg, lnqb, lnkvg, lnkvb, resW, resb);
    k24_fused<<<dim3(NCH, BB), 256, k24_smem>>>(xd);
    k3_combine<<<BB, 256>>>();
    k_attn<<<dim3(8, BB), 256>>>(out_attn);
    k5a_reduce<<<dim3(HH, BB), 256>>>(lnkvg, lnkvb);
    k5b_out<<<BB, 512>>>(Wv, out_ctx);
}

// round 10
// speedup vs baseline: 1.2203x; 1.2203x over previous
#include <cuda_runtime.h>
#include <math.h>

#define BB 64
#define PP 2048
#define LL 512
#define DM 512
#define HH 8
#define RCH 128               // rows per chunk (k2/k4)
#define NCH (PP / RCH)        // 16 chunks per batch
#define LN_EPS 1e-5f

// ---------------- scratch (device globals; no allocation) ----------------
__device__ float g_wg[BB * HH * LL];               // gamma-folded (1/8)W_k^T Q  [b][h][l]
__device__ float g_Wsum[BB * HH];
__device__ float g_wb[BB * HH];
__device__ float g_resid[BB * DM];
__device__ float g_scores[(size_t)BB * PP * HH];   // [b][p][h]  (4 MB, L2-resident)
__device__ float g_rstd[BB * PP];
__device__ float g_coeff[(size_t)BB * PP * HH];    // attn*rstd (globally normalized)
__device__ float g_cmax[BB * NCH * HH];
__device__ float g_cse[BB * NCH * HH];
__device__ float g_ca2[BB * NCH * HH];
__device__ float g_M[BB * HH];
__device__ float g_invZ[BB * HH];
__device__ float g_acc2[BB * HH];
__device__ float g_spart[(size_t)BB * NCH * HH * LL];  // 16 MB partial weighted sums
__device__ float g_svec[BB * HH * LL];

// ---------------- K1: per-batch setup (2 blocks per batch) -----------------
__global__ void k1_setup(const float* __restrict__ xt,
                         const float* __restrict__ Wq,
                         const float* __restrict__ Wk,
                         const float* __restrict__ lnqg, const float* __restrict__ lnqb,
                         const float* __restrict__ lnkvg, const float* __restrict__ lnkvb,
                         const float* __restrict__ resW, const float* __restrict__ resb) {
    int half = blockIdx.x, b = blockIdx.y, t = threadIdx.x;
    __shared__ float sx[LL];
    __shared__ float sq[LL];
    __shared__ float sQ[DM];
    __shared__ float sred[24];
    __shared__ float sws[4][2], swbp[4][2];

    float x0 = xt[b * LL + t];
    float x1 = xt[b * LL + t + 256];
    sx[t] = x0; sx[t + 256] = x1;

    float ps = x0 + x1;
    float pq = x0 * x0 + x1 * x1;
    #pragma unroll
    for (int o = 16; o; o >>= 1) {
        ps += __shfl_xor_sync(~0u, ps, o);
        pq += __shfl_xor_sync(~0u, pq, o);
    }
    if ((t & 31) == 0) { sred[t >> 5] = ps; sred[8 + (t >> 5)] = pq; }
    __syncthreads();
    if (t == 0) {
        float s = 0.f, q = 0.f;
        for (int i = 0; i < 8; i++) { s += sred[i]; q += sred[8 + i]; }
        float m = s * (1.0f / LL);
        float v = q * (1.0f / LL) - m * m;
        sred[16] = m;
        sred[17] = rsqrtf(v + LN_EPS);
    }
    __syncthreads();
    float mean = sred[16], rstd = sred[17];
    sq[t]       = (x0 - mean) * rstd * lnqg[t]       + lnqb[t];
    sq[t + 256] = (x1 - mean) * rstd * lnqg[t + 256] + lnqb[t + 256];
    __syncthreads();

    int d = half * 256 + t;
    {
        float qa = 0.f, ra = 0.f;
        #pragma unroll 8
        for (int l = 0; l < LL; l++) {
            qa = fmaf(sq[l], Wq[(size_t)l * DM + d], qa);
            ra = fmaf(sx[l], resW[(size_t)l * DM + d], ra);
        }
        sQ[d] = qa;
        g_resid[b * DM + d] = ra + resb[d];
    }
    __syncthreads();

    // fold W_k through Q for heads [half*4, half*4+4): warp-per-(head, l%2), coalesced
    {
        int w = t >> 5, lane = t & 31;
        int hl = w >> 1;
        int h  = half * 4 + hl;
        const float* Qh = sQ + h * 64;
        float q0 = Qh[lane], q1 = Qh[lane + 32];
        float wsum = 0.f, wbp = 0.f;
        for (int l = (w & 1); l < LL; l += 2) {
            const float* row = Wk + (size_t)l * DM + h * 64;
            float a = row[lane] * q0 + row[lane + 32] * q1;
            #pragma unroll
            for (int o = 16; o; o >>= 1) a += __shfl_xor_sync(~0u, a, o);
            float wv = a * 0.125f;
            float gw = wv * lnkvg[l];
            if (lane == 0) g_wg[((size_t)b * HH + h) * LL + l] = gw;
            wsum += gw;
            wbp  += wv * lnkvb[l];
        }
        if (lane == 0) { sws[hl][w & 1] = wsum; swbp[hl][w & 1] = wbp; }
    }
    __syncthreads();
    if (t < 4) {
        g_Wsum[b * HH + half * 4 + t] = sws[t][0] + sws[t][1];
        g_wb[b * HH + half * 4 + t]   = swbp[t][0] + swbp[t][1];
    }
}

// ---------------- K2: score pass + in-block chunk softmax stats ------------
__global__ void __launch_bounds__(256) k2_scores(const float* __restrict__ xd) {
    int c = blockIdx.x, b = blockIdx.y, t = threadIdx.x;
    int wid = t >> 5, lane = t & 31;
    __shared__ float4 swg4[HH * LL / 4];   // 16 KB
    __shared__ float sWs[HH], swb[HH];
    __shared__ float ssc[RCH * HH];        // 4 KB chunk scores
    __shared__ float srstd[RCH], smeanv[RCH];
    __shared__ float sredE[256], sredA[256], sredM[256];
    __shared__ float scmax[HH];

    {
        const float4* wgb = (const float4*)(g_wg + (size_t)b * HH * LL);
        for (int i = t; i < HH * LL / 4; i += 256) swg4[i] = wgb[i];
        if (t < HH) { sWs[t] = g_Wsum[b * HH + t]; swb[t] = g_wb[b * HH + t]; }
    }
    __syncthreads();

    int p0 = c * RCH;
    for (int r = wid; r < RCH; r += 8) {
        int p = p0 + r;
        const float4* xr = (const float4*)(xd + ((size_t)b * PP + p) * LL);
        float4 xv[4];
        #pragma unroll
        for (int j = 0; j < 4; j++) xv[j] = xr[lane + 32 * j];

        float s = 0.f, q = 0.f;
        #pragma unroll
        for (int j = 0; j < 4; j++) {
            s += xv[j].x + xv[j].y + xv[j].z + xv[j].w;
            q += xv[j].x * xv[j].x + xv[j].y * xv[j].y
               + xv[j].z * xv[j].z + xv[j].w * xv[j].w;
        }
        float dot[HH];
        #pragma unroll
        for (int h = 0; h < HH; h++) {
            float a = 0.f;
            #pragma unroll
            for (int j = 0; j < 4; j++) {
                float4 wv = swg4[h * 128 + lane + 32 * j];
                a = fmaf(xv[j].x, wv.x, a);
                a = fmaf(xv[j].y, wv.y, a);
                a = fmaf(xv[j].z, wv.z, a);
                a = fmaf(xv[j].w, wv.w, a);
            }
            dot[h] = a;
        }
        #pragma unroll
        for (int o = 16; o; o >>= 1) {
            s += __shfl_xor_sync(~0u, s, o);
            q += __shfl_xor_sync(~0u, q, o);
            #pragma unroll
            for (int h = 0; h < HH; h++) dot[h] += __shfl_xor_sync(~0u, dot[h], o);
        }
        float m  = s * (1.0f / LL);
        float v  = q * (1.0f / LL) - m * m;
        float r_ = rsqrtf(v + LN_EPS);
        if (lane == 0) {
            srstd[r] = r_; smeanv[r] = m;
            g_rstd[b * PP + p] = r_;
        }
        if (lane < HH) {
            float myd = 0.f, myWs = 0.f, mywb = 0.f;
            #pragma unroll
            for (int h = 0; h < HH; h++)
                if (lane == h) { myd = dot[h]; myWs = sWs[h]; mywb = swb[h]; }
            float sc = r_ * (myd - m * myWs) + mywb;
            g_scores[((size_t)b * PP + p) * HH + lane] = sc;
            ssc[r * HH + lane] = sc;
        }
    }
    __syncthreads();

    // chunk stats: h = t&7, rb = t>>3 (32 groups), 4 rows each
    int h = t & 7, rb = t >> 3;
    float mx = -1e30f;
    #pragma unroll
    for (int k = 0; k < 4; k++) mx = fmaxf(mx, ssc[(rb + 32 * k) * HH + h]);
    sredM[t] = mx;
    __syncthreads();
    if (t < 8) {
        float m = -1e30f;
        for (int k = 0; k < 32; k++) m = fmaxf(m, sredM[t + 8 * k]);
        scmax[t] = m;
    }
    __syncthreads();
    float M = scmax[h];
    float se = 0.f, sa = 0.f;
    #pragma unroll
    for (int k = 0; k < 4; k++) {
        int r = rb + 32 * k;
        float e = __expf(ssc[r * HH + h] - M);
        se += e;
        sa = fmaf(e, srstd[r] * smeanv[r], sa);
    }
    sredE[t] = se; sredA[t] = sa;
    __syncthreads();
    if (t < 8) {
        float e = 0.f, a = 0.f;
        for (int k = 0; k < 32; k++) { e += sredE[t + 8 * k]; a += sredA[t + 8 * k]; }
        int o = (b * NCH + c) * HH + t;
        g_cse[o] = e; g_ca2[o] = a; g_cmax[o] = scmax[t];
    }
}

// ---------------- K3c: combine 16 chunk stats per (b,h) --------------------
// Produces global M, invZ, and acc2 = sum_p attn_p * rstd_p * mean_p.
// (ca2_c * exp(M_c - M) * invZ sums exactly to acc2.)
__global__ void k3_combine() {
    int b = blockIdx.x, t = threadIdx.x;
    int h = t >> 5, lane = t & 31;          // warp per head
    size_t base = (size_t)b * NCH * HH;
    float m  = (lane < NCH) ? g_cmax[base + lane * HH + h] : -1e30f;
    float M = m;
    #pragma unroll
    for (int o = 16; o; o >>= 1) M = fmaxf(M, __shfl_xor_sync(~0u, M, o));
    float e  = (lane < NCH) ? __expf(m - M) : 0.f;
    float se = (lane < NCH) ? g_cse[base + lane * HH + h] : 0.f;
    float z = se * e;
    #pragma unroll
    for (int o = 16; o; o >>= 1) z += __shfl_xor_sync(~0u, z, o);
    float invZ = 1.0f / z;
    float a2 = (lane < NCH) ? g_ca2[base + lane * HH + h] * e * invZ : 0.f;
    #pragma unroll
    for (int o = 16; o; o >>= 1) a2 += __shfl_xor_sync(~0u, a2, o);
    if (lane == 0) {
        g_M[b * HH + h] = M;
        g_invZ[b * HH + h] = invZ;
        g_acc2[b * HH + h] = a2;
    }
}

// ---------------- K_attn: attn output (transposed) + coeff -----------------
// coeff = attn * rstd is FULLY normalized here (global M, invZ applied).
__global__ void k_attn(float* __restrict__ out_attn) {
    int tile = blockIdx.x, b = blockIdx.y, t = threadIdx.x;
    __shared__ float satt[256 * 9];
    __shared__ float sM[HH], sI[HH];
    __shared__ float sr[256];
    if (t < HH) { sM[t] = g_M[b * HH + t]; sI[t] = g_invZ[b * HH + t]; }
    sr[t] = g_rstd[b * PP + tile * 256 + t];
    __syncthreads();
    const float* sc = g_scores + ((size_t)b * PP + tile * 256) * HH;
    float*       cf = g_coeff  + ((size_t)b * PP + tile * 256) * HH;
    #pragma unroll
    for (int k = 0; k < 8; k++) {
        int il = k * 256 + t;
        int pl = il >> 3, h = il & 7;
        float a = __expf(sc[il] - sM[h]) * sI[h];
        satt[pl * 9 + h] = a;
        cf[il] = a * sr[pl];
    }
    __syncthreads();
    #pragma unroll
    for (int k = 0; k < 8; k++)
        out_attn[((size_t)b * HH + k) * PP + tile * 256 + t] = satt[t * 9 + k];
}

// ---------------- K4: weighted-sum pass (stream x_dynamic again) -----------
__global__ void __launch_bounds__(256) k4_wsum(const float* __restrict__ xd) {
    int c = blockIdx.x, b = blockIdx.y, t = threadIdx.x;
    int p0 = c * RCH;
    const float2* xrow2 = (const float2*)(xd + ((size_t)b * PP + p0) * LL);
    const float4* cf    = (const float4*)(g_coeff + ((size_t)b * PP + p0) * HH);

    float2 acc[HH];
    #pragma unroll
    for (int h = 0; h < HH; h++) acc[h] = make_float2(0.f, 0.f);

    #pragma unroll 4
    for (int r = 0; r < RCH; r++) {
        float4 c0 = __ldg(&cf[2 * r]);
        float4 c1 = __ldg(&cf[2 * r + 1]);
        float2 xv = xrow2[(size_t)r * 256 + t];
        float cc[8] = {c0.x, c0.y, c0.z, c0.w, c1.x, c1.y, c1.z, c1.w};
        #pragma unroll
        for (int h = 0; h < HH; h++) {
            acc[h].x = fmaf(cc[h], xv.x, acc[h].x);
            acc[h].y = fmaf(cc[h], xv.y, acc[h].y);
        }
    }
    #pragma unroll
    for (int h = 0; h < HH; h++) {
        float2* sp = (float2*)(g_spart + (((size_t)(b * NCH + c) * HH + h) * LL));
        sp[t] = acc[h];
    }
}

// ---------------- K5a: SUM partials per (b,h) (coeff already normalized), --
// ---------------- then LN gamma/beta + acc2 correction ---------------------
__global__ void k5a_reduce(const float* __restrict__ lnkvg,
                           const float* __restrict__ lnkvb) {
    int h = blockIdx.x, b = blockIdx.y, t = threadIdx.x;

    float a0 = 0.f, a1 = 0.f;
    const float* sp = g_spart + ((size_t)(b * NCH) * HH + h) * LL;
    #pragma unroll
    for (int c = 0; c < NCH; c++) {
        const float* row = sp + (size_t)c * HH * LL;
        a0 += row[t];
        a1 += row[t + 256];
    }
    float acc2 = g_acc2[b * HH + h];
    float* dst = g_svec + ((size_t)b * HH + h) * LL;
    dst[t]       = lnkvg[t]       * (a0 - acc2) + lnkvb[t];
    dst[t + 256] = lnkvg[t + 256] * (a1 - acc2) + lnkvb[t + 256];
}

// ---------------- K5b: V-GEMV + residual add -------------------------------
__global__ void k5b_out(const float* __restrict__ Wv,
                        float* __restrict__ out_ctx) {
    int b = blockIdx.x, t = threadIdx.x;
    __shared__ float ss[HH * LL];
    const float4* sv = (const float4*)(g_svec + (size_t)b * HH * LL);
    float4* ss4 = (float4*)ss;
    for (int i = t; i < HH * LL / 4; i += 512) ss4[i] = sv[i];
    __syncthreads();

    int d = t;
    int h = d >> 6;
    const float* sh = ss + h * LL;
    float a = 0.f;
    #pragma unroll 8
    for (int l = 0; l < LL; l++) a = fmaf(sh[l], Wv[(size_t)l * DM + d], a);
    out_ctx[b * DM + d] = g_resid[b * DM + d] + a;
}

// ---------------- launch ---------------------------------------------------
extern "C" void kernel_launch(void* const* d_in, const int* in_sizes, int n_in,
                              void* d_out, int out_size) {
    const float* xt    = (const float*)d_in[0];
    const float* xd    = (const float*)d_in[1];
    const float* Wq    = (const float*)d_in[3];
    const float* Wk    = (const float*)d_in[4];
    const float* Wv    = (const float*)d_in[5];
    const float* lnqg  = (const float*)d_in[6];
    const float* lnqb  = (const float*)d_in[7];
    const float* lnkvg = (const float*)d_in[8];
    const float* lnkvb = (const float*)d_in[9];
    const float* resW  = (const float*)d_in[10];
    const float* resb  = (const float*)d_in[11];

    float* out      = (float*)d_out;
    float* out_ctx  = out;                  // (B, DM)
    float* out_attn = out + BB * DM;        // (B, H, 1, P)

    k1_setup<<<dim3(2, BB), 256>>>(xt, Wq, Wk, lnqg, lnqb, lnkvg, lnkvb, resW, resb);
    k2_scores<<<dim3(NCH, BB), 256>>>(xd);
    k3_combine<<<BB, 256>>>();
    k_attn<<<dim3(8, BB), 256>>>(out_attn);
    k4_wsum<<<dim3(NCH, BB), 256>>>(xd);
    k5a_reduce<<<dim3(HH, BB), 256>>>(lnkvg, lnkvb);
    k5b_out<<<BB, 512>>>(Wv, out_ctx);
}